// round 14
// baseline (speedup 1.0000x reference)
#include <cuda_runtime.h>
#include <cstdint>
#include <cstddef>

#define DM 63
#define DD 64
#define NR_MAX 256
#define B_MAX 2048
#define TMAIN 128
#define TILE  128
#define WSTR  65   // smem row stride
#define TREL  256

// ---- scratch (static __device__ globals; no runtime allocation) ----
__device__ float g_Wg[2][(size_t)NR_MAX * DD * DD];   // gelu(W) rows [j*64+k], row 63 zeroed
__device__ float g_iv[2][NR_MAX * DD];                // 2/s_j (j=63 -> 0)
__device__ float g_G [2][NR_MAX * 224];               // intra-segment Gram pairs
__device__ float g_off[2][NR_MAX * DD];               // mobius offset per relation
__device__ float g_off2[2][NR_MAX];                   // sum(off^2)
__device__ float g_p63[NR_MAX * DD];                  // tail: P e62 (unscaled last col), [0]=0
__device__ float g_ofu[NR_MAX * DD];                  // tail: P D off_sp, [0]=off0
__device__ float g_ttl[B_MAX * DD];                   // tail: P D th_sp per b, [0]=0
__device__ float g_sc[B_MAX * 8];                     // {O2m,OTm,T2m,thb,th0,off0,off2,-}

__device__ __constant__ int c_pa[28] = {0,0,1,0,1,2,0,1,2,3,0,1,2,3,4,0,1,2,3,4,5,0,1,2,3,4,5,6};
__device__ __constant__ int c_pb[28] = {1,2,2,3,3,3,4,4,4,4,5,5,5,5,5,6,6,6,6,6,6,7,7,7,7,7,7,7};

__device__ __forceinline__ float gelu_exact(float x) {
    return 0.5f * x * (1.0f + erff(x * 0.70710678118654752f));
}

__device__ __forceinline__ float wbfly(float v) {
    #pragma unroll
    for (int o = 16; o; o >>= 1) v += __shfl_xor_sync(0xffffffffu, v, o);
    return v;
}

// ============================================================================
// Rank-8 reflection segment applied to a warp-held vector (see R12 notes).
// ============================================================================
template<bool FWD>
__device__ __forceinline__ void apply_seg(
    float& v0, float& v1, int lane,
    const float* __restrict__ W, int wstride,
    const float* __restrict__ iv, const float* __restrict__ G, int seg)
{
    int lo = seg * 8;
    float w0[8], w1[8], d[8], ivv[8], g[28];
    #pragma unroll
    for (int i = 0; i < 8; i++) {
        const float* row = W + (size_t)(lo + i) * wstride;
        w0[i] = (lane >= 1) ? row[lane - 1] : 0.0f;
        w1[i] = row[lane + 31];
        ivv[i] = iv[lo + i];
    }
    #pragma unroll
    for (int p = 0; p < 28; p++) g[p] = G[seg * 28 + p];
    #pragma unroll
    for (int i = 0; i < 8; i++) d[i] = fmaf(w0[i], v0, w1[i] * v1);
    #pragma unroll
    for (int o = 16; o; o >>= 1) {
        #pragma unroll
        for (int i = 0; i < 8; i++) d[i] += __shfl_xor_sync(0xffffffffu, d[i], o);
    }
    float c[8];
    if (FWD) {
        c[0] = d[0] * ivv[0];
        c[1] = (d[1] - c[0]*g[0]) * ivv[1];
        c[2] = (d[2] - c[0]*g[1] - c[1]*g[2]) * ivv[2];
        c[3] = (d[3] - c[0]*g[3] - c[1]*g[4] - c[2]*g[5]) * ivv[3];
        c[4] = (d[4] - c[0]*g[6] - c[1]*g[7] - c[2]*g[8] - c[3]*g[9]) * ivv[4];
        c[5] = (d[5] - c[0]*g[10] - c[1]*g[11] - c[2]*g[12] - c[3]*g[13] - c[4]*g[14]) * ivv[5];
        c[6] = (d[6] - c[0]*g[15] - c[1]*g[16] - c[2]*g[17] - c[3]*g[18] - c[4]*g[19] - c[5]*g[20]) * ivv[6];
        c[7] = (d[7] - c[0]*g[21] - c[1]*g[22] - c[2]*g[23] - c[3]*g[24] - c[4]*g[25] - c[5]*g[26] - c[6]*g[27]) * ivv[7];
    } else {
        c[7] = d[7] * ivv[7];
        c[6] = (d[6] - c[7]*g[27]) * ivv[6];
        c[5] = (d[5] - c[7]*g[26] - c[6]*g[20]) * ivv[5];
        c[4] = (d[4] - c[7]*g[25] - c[6]*g[19] - c[5]*g[14]) * ivv[4];
        c[3] = (d[3] - c[7]*g[24] - c[6]*g[18] - c[5]*g[13] - c[4]*g[9]) * ivv[3];
        c[2] = (d[2] - c[7]*g[23] - c[6]*g[17] - c[5]*g[12] - c[4]*g[8] - c[3]*g[5]) * ivv[2];
        c[1] = (d[1] - c[7]*g[22] - c[6]*g[16] - c[5]*g[11] - c[4]*g[7] - c[3]*g[4] - c[2]*g[2]) * ivv[1];
        c[0] = (d[0] - c[7]*g[21] - c[6]*g[15] - c[5]*g[10] - c[4]*g[6] - c[3]*g[3] - c[2]*g[1] - c[1]*g[0]) * ivv[0];
    }
    float s0 = 0.0f, s1 = 0.0f;
    #pragma unroll
    for (int i = 0; i < 8; i++) { s0 = fmaf(c[i], w0[i], s0); s1 = fmaf(c[i], w1[i], s1); }
    v0 -= s0; v1 -= s1;
}

// ============================================================================
// K1: per-relation precompute. grid (NR, 2), block 256.
//   gelu over 256 threads; 287 dots as warp-collective butterflies (8 warps);
//   offsets by warp 0 (2 comps/lane); side1 chains on warps 0/1.
// ============================================================================
__global__ void __launch_bounds__(TREL) k_rel(
    const float* __restrict__ Wh,  const float* __restrict__ Wtt,
    const float* __restrict__ rch, const float* __restrict__ dirh,
    const float* __restrict__ rct, const float* __restrict__ dirt,
    const float* __restrict__ fsh, const float* __restrict__ fst)
{
    int r    = blockIdx.x;
    int side = blockIdx.y;
    const float* Wemb = side ? Wtt  : Wh;
    const float* rc   = side ? rct  : rch;
    const float* dw   = side ? dirt : dirh;
    float fs          = side ? fst[0] : fsh[0];

    __shared__ float WgS[DD * WSTR];
    __shared__ float ivS[DD];
    __shared__ float GS[224];
    __shared__ float offS[DD];

    int tid = threadIdx.x, lane = tid & 31, wid = tid >> 5;
    float* gW = &g_Wg[side][(size_t)r * DD * DD];

    // pads: row 63 (smem+global), col 63 (smem; col 64 never read)
    for (int k = tid; k < WSTR; k += TREL) WgS[63 * WSTR + k] = 0.0f;
    for (int k = tid; k < DD;   k += TREL) gW[63 * DD + k]    = 0.0f;
    if (tid < 63) WgS[tid * WSTR + 63] = 0.0f;

    // gelu 63x63 -> smem + global
    const float* wb = Wemb + (size_t)r * DM * DM;
    for (int idx = tid; idx < DM * DM; idx += TREL) {
        int j = idx / DM, k = idx - j * DM;
        float v = gelu_exact(wb[idx]);
        WgS[j * WSTR + k] = v;
        gW[j * DD + k]    = v;
    }
    __syncthreads();

    // 287 warp-collective dots: t<63 -> inv2s norms; t>=63 -> Gram pairs
    for (int t = wid; t < 287; t += 8) {
        const float *ra, *rb;
        if (t < 63) {
            ra = rb = WgS + t * WSTR;
        } else {
            int p = t - 63, s = p / 28, q = p - s * 28;
            ra = WgS + (s * 8 + c_pa[q]) * WSTR;
            rb = WgS + (s * 8 + c_pb[q]) * WSTR;
        }
        float pr = fmaf(ra[lane], rb[lane], ra[lane + 32] * rb[lane + 32]);
        pr = wbfly(pr);
        if (lane == 0) {
            if (t < 63) {
                float iv = 2.0f / pr;
                ivS[t] = iv;
                g_iv[side][r * DD + t] = iv;
            } else {
                GS[t - 63] = pr;
                g_G[side][r * 224 + t - 63] = pr;
            }
        }
    }
    if (tid == 0) { ivS[63] = 0.0f; g_iv[side][r * DD + 63] = 0.0f; }

    // offset = expmap(c, 0.1 * normalize(d + <c,d> c)) — warp 0, 2 comps/lane
    if (wid == 0) {
        float cv0 = rc[r * DD + lane],      cv1 = rc[r * DD + lane + 32];
        float dv0 = dw[r * DD + lane],      dv1 = dw[r * DD + lane + 32];
        float inner = wbfly(fmaf(cv0, dv0, cv1 * dv1));
        float t0 = fmaf(inner, cv0, dv0), t1 = fmaf(inner, cv1, dv1);
        float tn2 = wbfly(fmaf(t0, t0, t1 * t1));
        float inv = 1.0f / (sqrtf(tn2) + 1e-6f);
        float u0v = 0.1f * t0 * inv, u1v = 0.1f * t1 * inv;
        float su2 = wbfly(fmaf(u0v, u0v, u1v * u1v));
        float ut  = __shfl_sync(0xffffffffu, u0v, 0);
        float lin = su2 - 2.0f * ut * ut;
        float nrm = fminf(sqrtf(fmaxf(lin, 1e-8f)), 2.5f);
        float ch = coshf(nrm), sh = sinhf(nrm) / nrm;
        float o0 = fmaf(ch, cv0, sh * u0v);
        float o1 = fmaf(ch, cv1, sh * u1v);
        offS[lane] = o0;  offS[lane + 32] = o1;
        g_off[side][r * DD + lane]      = o0;
        g_off[side][r * DD + lane + 32] = o1;
        float o2 = wbfly(fmaf(o0, o0, o1 * o1));
        if (lane == 0) g_off2[side][r] = o2;
    }
    __syncthreads();

    if (side == 1) {
        if (wid == 0) {
            // õ = P D off_sp : reverse chain on flip-scaled offset spatial part
            float v0 = (lane >= 1) ? offS[lane] : 0.0f;
            float v1 = offS[lane + 32];
            if (lane == 31) v1 *= fs;
            #pragma unroll 1
            for (int s = 7; s >= 0; s--) apply_seg<false>(v0, v1, lane, WgS, WSTR, ivS, GS, s);
            if (lane == 0) g_ofu[r * DD] = offS[0];
            else           g_ofu[r * DD + lane] = v0;
            g_ofu[r * DD + lane + 32] = v1;
        } else if (wid == 1) {
            // p63 = P e62 : reverse chain on unit vector (no flip)
            float v0 = 0.0f;
            float v1 = (lane == 31) ? 1.0f : 0.0f;
            #pragma unroll 1
            for (int s = 7; s >= 0; s--) apply_seg<false>(v0, v1, lane, WgS, WSTR, ivS, GS, s);
            g_p63[r * DD + lane] = (lane >= 1) ? v0 : 0.0f;
            g_p63[r * DD + lane + 32] = v1;
        }
    }
}

// ============================================================================
// K2: per-batch-row head pipeline. grid B, ONE warp. (unchanged from R12)
// ============================================================================
__global__ void __launch_bounds__(32) k_head(
    const float* __restrict__ ent, const float* __restrict__ bias_head,
    const int* __restrict__ u_idx, const int* __restrict__ r_idx,
    const float* __restrict__ fsh, const float* __restrict__ fst)
{
    int b = blockIdx.x, l = threadIdx.x;
    int u = u_idx[b], r = r_idx[b];
    float fsH = fsh[0], fsT = fst[0];

    float v0 = ent[(size_t)u * DD + l];
    float v1 = ent[(size_t)u * DD + l + 32];

    {   // y_sp = D (P^T x_sp): forward chain, then flip comp62
        const float* W  = &g_Wg[0][(size_t)r * DD * DD];
        const float* iv = &g_iv[0][r * DD];
        const float* G  = &g_G[0][r * 224];
        #pragma unroll 1
        for (int s = 0; s < 8; s++) apply_seg<true>(v0, v1, l, W, DD, iv, G, s);
    }
    if (l == 31) v1 *= fsH;

    // mobius_add(y, off_h)
    float oh0 = g_off[0][r * DD + l];
    float oh1 = g_off[0][r * DD + l + 32];
    float x2 = fmaf(v0, v0, v1 * v1);
    float xy = fmaf(v0, oh0, v1 * oh1);
    #pragma unroll
    for (int o = 16; o; o >>= 1) {
        x2 += __shfl_xor_sync(0xffffffffu, x2, o);
        xy += __shfl_xor_sync(0xffffffffu, xy, o);
    }
    float y2  = g_off2[0][r];
    float A   = 1.0f + 2.0f * xy + y2;
    float Bc  = 1.0f - x2;
    float den = 1.0f + 2.0f * xy + x2 * y2 + 1e-15f;
    float rd  = 1.0f / den;
    float th0c = fmaf(A, v0, Bc * oh0) * rd;
    float th1c = fmaf(A, v1, Bc * oh1) * rd;

    // t~ = P D th_sp
    float t0 = th0c, t1 = th1c;
    if (l == 31) t1 *= fsT;
    {
        const float* W  = &g_Wg[1][(size_t)r * DD * DD];
        const float* iv = &g_iv[1][r * DD];
        const float* G  = &g_G[1][r * 224];
        #pragma unroll 1
        for (int s = 7; s >= 0; s--) apply_seg<false>(t0, t1, l, W, DD, iv, G, s);
    }
    g_ttl[b * DD + l]      = (l >= 1) ? t0 : 0.0f;
    g_ttl[b * DD + l + 32] = t1;

    // scalar pack
    float ot0 = g_off[1][r * DD + l];
    float ot1 = g_off[1][r * DD + l + 32];
    float e0  = (l >= 1) ? 1.0f : 0.0f;
    float pO2 = fmaf(e0 * ot0, ot0,  ot1 * ot1);
    float pOT = fmaf(e0 * ot0, th0c, ot1 * th1c);
    float pT2 = fmaf(e0 * th0c, th0c, th1c * th1c);
    #pragma unroll
    for (int o = 16; o; o >>= 1) {
        pO2 += __shfl_xor_sync(0xffffffffu, pO2, o);
        pOT += __shfl_xor_sync(0xffffffffu, pOT, o);
        pT2 += __shfl_xor_sync(0xffffffffu, pT2, o);
    }
    if (l == 0) {
        float* sc = &g_sc[b * 8];
        sc[0] = pO2;
        sc[1] = pOT;
        sc[2] = pT2;
        sc[3] = tanhf(bias_head[u]);
        sc[4] = th0c;
        sc[5] = ot0;
        sc[6] = g_off2[1][r];
        sc[7] = 0.0f;
    }
}

// ============================================================================
// K3: main scoring (unchanged). grid (B, N/128), block 128.
// ============================================================================
__global__ void __launch_bounds__(TMAIN) k_main(
    const float* __restrict__ ent, const float* __restrict__ bias_tail,
    const int* __restrict__ r_idx, const int* __restrict__ v_idx,
    const float* __restrict__ fst,
    float* __restrict__ out, int N)
{
    __shared__ __align__(16) float4 res4[TILE];
    __shared__ int   vs[TILE];
    __shared__ __align__(16) float pv[DD], ov[DD], tl[DD];
    __shared__ float scs[8];

    int b     = blockIdx.x;
    int tbase = blockIdx.y * TILE;
    int tid   = threadIdx.x;
    if (tbase >= N) return;
    int nt = min(TILE, N - tbase);
    int r  = r_idx[b];

    if (tid < DD) {
        pv[tid] = g_p63[r * DD + tid];
        ov[tid] = g_ofu[r * DD + tid];
        tl[tid] = g_ttl[b * DD + tid];
    }
    if (tid < 8) scs[tid] = g_sc[b * 8 + tid];
    vs[tid] = (tid < nt) ? v_idx[b * N + tbase + tid] : 0;
    float fsv  = fst[0];
    float fsm1 = fsv * fsv - 1.0f;
    __syncthreads();

    float btraw = bias_tail[vs[tid < nt ? tid : 0]];

    int h = tid & 7;
    int g = tid >> 3;
    float4 pa = ((const float4*)pv)[h], pb = ((const float4*)pv)[h + 8];
    float4 oa = ((const float4*)ov)[h], ob = ((const float4*)ov)[h + 8];
    float4 ta = ((const float4*)tl)[h], tb = ((const float4*)tl)[h + 8];

    #pragma unroll
    for (int i = 0; i < 8; i++) {
        int row = i * 16 + g;
        const float4* xr = (const float4*)(ent + (size_t)vs[row] * DD);
        float4 xa = xr[h];
        float4 xb = xr[h + 8];

        float s1 = fmaf(xa.x, pa.x, fmaf(xa.y, pa.y, fmaf(xa.z, pa.z, xa.w * pa.w)));
        s1 = fmaf(xb.x, pb.x, fmaf(xb.y, pb.y, fmaf(xb.z, pb.z, fmaf(xb.w, pb.w, s1))));
        float s2 = fmaf(xa.x, oa.x, fmaf(xa.y, oa.y, fmaf(xa.z, oa.z, xa.w * oa.w)));
        s2 = fmaf(xb.x, ob.x, fmaf(xb.y, ob.y, fmaf(xb.z, ob.z, fmaf(xb.w, ob.w, s2))));
        float s3 = fmaf(xa.x, ta.x, fmaf(xa.y, ta.y, fmaf(xa.z, ta.z, xa.w * ta.w)));
        s3 = fmaf(xb.x, tb.x, fmaf(xb.y, tb.y, fmaf(xb.z, tb.z, fmaf(xb.w, tb.w, s3))));

        #pragma unroll
        for (int o = 4; o; o >>= 1) {
            s1 += __shfl_down_sync(0xffffffffu, s1, o, 8);
            s2 += __shfl_down_sync(0xffffffffu, s2, o, 8);
            s3 += __shfl_down_sync(0xffffffffu, s3, o, 8);
        }
        if (h == 0) res4[row] = make_float4(s1, s2, s3, xa.x);
    }
    __syncthreads();

    if (tid < nt) {
        float4 rr = res4[tid];
        float s1 = rr.x, syo = rr.y, syt = rr.z, y0 = rr.w;

        float O2m = scs[0], OTm = scs[1], T2m = scs[2], thb = scs[3];
        float th0 = scs[4], off0 = scs[5], off2 = scs[6];

        float syy_m = fmaf(fsm1, s1 * s1, fmaf(y0, y0, -1.0f));
        float syy   = syy_m + y0 * y0;

        float A   = 1.0f + 2.0f * syo + off2;
        float Bv  = 1.0f - syy;
        float den = 1.0f + 2.0f * syo + syy * off2 + 1e-15f;
        float rd  = 1.0f / den;
        float a   = A * rd, bs = Bv * rd;
        float d0  = fmaf(a, y0, fmaf(bs, off0, -th0));
        float cross = fmaf(bs, syo - y0 * off0, -syt);
        float bterm = fmaf(bs, fmaf(bs, O2m, -2.0f * OTm), T2m);
        float sum1  = fmaf(a * a, syy_m, fmaf(2.0f * a, cross, bterm));
        float mkv   = sum1 - d0 * d0;

        out[(size_t)b * N + tbase + tid] = 8.0f - mkv + thb + tanhf(btraw);
    }
}

// ============================================================================
extern "C" void kernel_launch(void* const* d_in, const int* in_sizes, int n_in,
                              void* d_out, int out_size)
{
    (void)n_in; (void)out_size;
    const float* ent  = (const float*)d_in[0];
    const float* Wh   = (const float*)d_in[1];
    const float* Wtt  = (const float*)d_in[2];
    const float* rch  = (const float*)d_in[3];
    const float* dirh = (const float*)d_in[4];
    const float* rct  = (const float*)d_in[5];
    const float* dirt = (const float*)d_in[6];
    const float* bh   = (const float*)d_in[7];
    const float* bt   = (const float*)d_in[8];
    const float* fsh  = (const float*)d_in[9];
    const float* fst  = (const float*)d_in[10];
    const int* u_idx  = (const int*)d_in[11];
    const int* r_idx  = (const int*)d_in[12];
    const int* v_idx  = (const int*)d_in[13];
    float* out = (float*)d_out;

    int NR = in_sizes[3] / DD;       // 237
    int B  = in_sizes[11];           // 1024
    int N  = in_sizes[13] / B;       // 512
    int S  = (N + TILE - 1) / TILE;  // 4

    k_rel<<<dim3(NR, 2), TREL>>>(Wh, Wtt, rch, dirh, rct, dirt, fsh, fst);
    k_head<<<B, 32>>>(ent, bh, u_idx, r_idx, fsh, fst);
    k_main<<<dim3(B, S), TMAIN>>>(ent, bt, r_idx, v_idx, fst, out, N);
}

// round 15
// speedup vs baseline: 1.4000x; 1.4000x over previous
#include <cuda_runtime.h>
#include <cstdint>
#include <cstddef>

#define DM 63
#define DD 64
#define NR_MAX 256
#define B_MAX 2048
#define TMAIN 128
#define TILE  128
#define WSTR  65

// ---- scratch (static __device__ globals; no runtime allocation) ----
__device__ float g_Wg[2][(size_t)NR_MAX * DD * DD];   // gelu(W) rows [j*64+k], row 63 + col 63 zero
__device__ float g_iv[2][NR_MAX * DD];                // 2/s_j (j=63 -> 0)
__device__ float g_G [2][NR_MAX * 224];               // intra-segment Gram pairs
__device__ float g_off[2][NR_MAX * DD];               // mobius offset per relation
__device__ float g_off2[2][NR_MAX];                   // sum(off^2)
__device__ float g_p63[NR_MAX * DD];                  // tail: P e62 (unscaled last col), [0]=0
__device__ float g_ofu[NR_MAX * DD];                  // tail: P D off_sp, [0]=off0
__device__ float g_ttl[B_MAX * DD];                   // tail: P D th_sp per b, [0]=0
__device__ float g_sc[B_MAX * 8];                     // {O2m,OTm,T2m,thb,th0,off0,off2,-}

__device__ __constant__ int c_pa[28] = {0,0,1,0,1,2,0,1,2,3,0,1,2,3,4,0,1,2,3,4,5,0,1,2,3,4,5,6};
__device__ __constant__ int c_pb[28] = {1,2,2,3,3,3,4,4,4,4,5,5,5,5,5,6,6,6,6,6,6,7,7,7,7,7,7,7};

__device__ __forceinline__ float gelu_exact(float x) {
    return 0.5f * x * (1.0f + erff(x * 0.70710678118654752f));
}

__device__ __forceinline__ float wbfly(float v) {
    #pragma unroll
    for (int o = 16; o; o >>= 1) v += __shfl_xor_sync(0xffffffffu, v, o);
    return v;
}

// ============================================================================
// Rank-8 reflection segment applied to a warp-held vector.
// lane l owns full-vec comps l (slot0) and l+32 (slot1); chain comp c lives at
// full idx c+1. FWD: i=0..7 (y = H1..H63 x). REV: i=7..0 (P v). Row 63 pad
// (w=0, iv=0) makes the last step a no-op.
// ============================================================================
template<bool FWD>
__device__ __forceinline__ void apply_seg(
    float& v0, float& v1, int lane,
    const float* __restrict__ W, int wstride,
    const float* __restrict__ iv, const float* __restrict__ G, int seg)
{
    int lo = seg * 8;
    float w0[8], w1[8], d[8], ivv[8], g[28];
    #pragma unroll
    for (int i = 0; i < 8; i++) {
        const float* row = W + (size_t)(lo + i) * wstride;
        w0[i] = (lane >= 1) ? row[lane - 1] : 0.0f;
        w1[i] = row[lane + 31];
        ivv[i] = iv[lo + i];
    }
    #pragma unroll
    for (int p = 0; p < 28; p++) g[p] = G[seg * 28 + p];
    #pragma unroll
    for (int i = 0; i < 8; i++) d[i] = fmaf(w0[i], v0, w1[i] * v1);
    #pragma unroll
    for (int o = 16; o; o >>= 1) {
        #pragma unroll
        for (int i = 0; i < 8; i++) d[i] += __shfl_xor_sync(0xffffffffu, d[i], o);
    }
    float c[8];
    if (FWD) {
        c[0] = d[0] * ivv[0];
        c[1] = (d[1] - c[0]*g[0]) * ivv[1];
        c[2] = (d[2] - c[0]*g[1] - c[1]*g[2]) * ivv[2];
        c[3] = (d[3] - c[0]*g[3] - c[1]*g[4] - c[2]*g[5]) * ivv[3];
        c[4] = (d[4] - c[0]*g[6] - c[1]*g[7] - c[2]*g[8] - c[3]*g[9]) * ivv[4];
        c[5] = (d[5] - c[0]*g[10] - c[1]*g[11] - c[2]*g[12] - c[3]*g[13] - c[4]*g[14]) * ivv[5];
        c[6] = (d[6] - c[0]*g[15] - c[1]*g[16] - c[2]*g[17] - c[3]*g[18] - c[4]*g[19] - c[5]*g[20]) * ivv[6];
        c[7] = (d[7] - c[0]*g[21] - c[1]*g[22] - c[2]*g[23] - c[3]*g[24] - c[4]*g[25] - c[5]*g[26] - c[6]*g[27]) * ivv[7];
    } else {
        c[7] = d[7] * ivv[7];
        c[6] = (d[6] - c[7]*g[27]) * ivv[6];
        c[5] = (d[5] - c[7]*g[26] - c[6]*g[20]) * ivv[5];
        c[4] = (d[4] - c[7]*g[25] - c[6]*g[19] - c[5]*g[14]) * ivv[4];
        c[3] = (d[3] - c[7]*g[24] - c[6]*g[18] - c[5]*g[13] - c[4]*g[9]) * ivv[3];
        c[2] = (d[2] - c[7]*g[23] - c[6]*g[17] - c[5]*g[12] - c[4]*g[8] - c[3]*g[5]) * ivv[2];
        c[1] = (d[1] - c[7]*g[22] - c[6]*g[16] - c[5]*g[11] - c[4]*g[7] - c[3]*g[4] - c[2]*g[2]) * ivv[1];
        c[0] = (d[0] - c[7]*g[21] - c[6]*g[15] - c[5]*g[10] - c[4]*g[6] - c[3]*g[3] - c[2]*g[1] - c[1]*g[0]) * ivv[0];
    }
    float s0 = 0.0f, s1 = 0.0f;
    #pragma unroll
    for (int i = 0; i < 8; i++) { s0 = fmaf(c[i], w0[i], s0); s1 = fmaf(c[i], w1[i], s1); }
    v0 -= s0; v1 -= s1;
}

// ============================================================================
// K1a: per-segment gelu + norms + Gram. grid (NR, 2, 8), block 64.
//   3792 blocks; each handles 8 W rows: 504 gelu, then 36 serial ILP-4 dots
//   over 64 threads from a 2 KB smem tile.
// ============================================================================
__global__ void __launch_bounds__(64) k_seg(
    const float* __restrict__ Wh, const float* __restrict__ Wtt)
{
    int r = blockIdx.x, side = blockIdx.y, seg = blockIdx.z;
    const float* Wemb = side ? Wtt : Wh;
    __shared__ __align__(16) float WgS[8][WSTR];

    int tid = threadIdx.x;
    float* gW = &g_Wg[side][(size_t)r * DD * DD];
    int j0 = seg * 8;

    // gelu 8 rows -> smem + global (pads: j==63 or k==63 -> 0)
    const float* wb = Wemb + (size_t)r * DM * DM;
    #pragma unroll
    for (int ii = 0; ii < 8; ii++) {
        int idx = ii * 64 + tid;          // 0..511
        int jj = idx >> 6, k = idx & 63;
        int j = j0 + jj;
        float v = 0.0f;
        if (j < DM && k < DM) v = gelu_exact(wb[j * DM + k]);
        WgS[jj][k] = v;
        gW[(size_t)j * DD + k] = v;
    }
    __syncthreads();

    // 36 tasks: t<8 norms -> iv; t in [8,36) Gram pairs
    if (tid < 36) {
        const float *ra, *rb;
        if (tid < 8) { ra = rb = WgS[tid]; }
        else { int q = tid - 8; ra = WgS[c_pa[q]]; rb = WgS[c_pb[q]]; }
        float a0 = 0, a1 = 0, a2 = 0, a3 = 0;
        #pragma unroll
        for (int k = 0; k < DD; k += 4) {
            a0 = fmaf(ra[k    ], rb[k    ], a0);
            a1 = fmaf(ra[k + 1], rb[k + 1], a1);
            a2 = fmaf(ra[k + 2], rb[k + 2], a2);
            a3 = fmaf(ra[k + 3], rb[k + 3], a3);
        }
        float dot = (a0 + a1) + (a2 + a3);
        if (tid < 8) {
            int j = j0 + tid;
            g_iv[side][r * DD + j] = (j < DM) ? 2.0f / dot : 0.0f;
        } else {
            g_G[side][r * 224 + seg * 28 + (tid - 8)] = dot;
        }
    }
}

// ============================================================================
// K1b: offsets + side-1 reverse chains. grid (NR, 2), block 64.
//   warp0: expmap offset (reg-held) then õ chain; warp1: p63 chain.
// ============================================================================
__global__ void __launch_bounds__(64) k_offchain(
    const float* __restrict__ rch, const float* __restrict__ dirh,
    const float* __restrict__ rct, const float* __restrict__ dirt,
    const float* __restrict__ fsh, const float* __restrict__ fst)
{
    int r    = blockIdx.x;
    int side = blockIdx.y;
    const float* rc = side ? rct  : rch;
    const float* dw = side ? dirt : dirh;
    float fs        = side ? fst[0] : fsh[0];

    __shared__ float ivS[DD];
    __shared__ float GS[224];

    int tid = threadIdx.x, lane = tid & 31, wid = tid >> 5;

    // stage iv + G (288 floats)
    ivS[tid] = g_iv[side][r * DD + tid];
    for (int i = tid; i < 224; i += 64) GS[i] = g_G[side][r * 224 + i];
    __syncthreads();

    if (wid == 0) {
        // offset = expmap(c, 0.1 * normalize(d + <c,d> c)), 2 comps/lane
        float cv0 = rc[r * DD + lane], cv1 = rc[r * DD + lane + 32];
        float dv0 = dw[r * DD + lane], dv1 = dw[r * DD + lane + 32];
        float inner = wbfly(fmaf(cv0, dv0, cv1 * dv1));
        float t0 = fmaf(inner, cv0, dv0), t1 = fmaf(inner, cv1, dv1);
        float tn2 = wbfly(fmaf(t0, t0, t1 * t1));
        float inv = 1.0f / (sqrtf(tn2) + 1e-6f);
        float u0v = 0.1f * t0 * inv, u1v = 0.1f * t1 * inv;
        float su2 = wbfly(fmaf(u0v, u0v, u1v * u1v));
        float ut  = __shfl_sync(0xffffffffu, u0v, 0);
        float lin = su2 - 2.0f * ut * ut;
        float nrm = fminf(sqrtf(fmaxf(lin, 1e-8f)), 2.5f);
        float ch = coshf(nrm), sh = sinhf(nrm) / nrm;
        float o0 = fmaf(ch, cv0, sh * u0v);
        float o1 = fmaf(ch, cv1, sh * u1v);
        g_off[side][r * DD + lane]      = o0;
        g_off[side][r * DD + lane + 32] = o1;
        float o2 = wbfly(fmaf(o0, o0, o1 * o1));
        if (lane == 0) g_off2[side][r] = o2;

        if (side == 1) {
            // õ = P D off_sp : reverse chain on flip-scaled offset spatial part
            float off0save = __shfl_sync(0xffffffffu, o0, 0);
            float v0 = (lane >= 1) ? o0 : 0.0f;
            float v1 = o1;
            if (lane == 31) v1 *= fs;
            const float* W = &g_Wg[1][(size_t)r * DD * DD];
            #pragma unroll 1
            for (int s = 7; s >= 0; s--) apply_seg<false>(v0, v1, lane, W, DD, ivS, GS, s);
            g_ofu[r * DD + lane]      = (lane >= 1) ? v0 : off0save;
            g_ofu[r * DD + lane + 32] = v1;
        }
    } else if (wid == 1 && side == 1) {
        // p63 = P e62 : reverse chain on unit vector (no flip)
        float v0 = 0.0f;
        float v1 = (lane == 31) ? 1.0f : 0.0f;
        const float* W = &g_Wg[1][(size_t)r * DD * DD];
        #pragma unroll 1
        for (int s = 7; s >= 0; s--) apply_seg<false>(v0, v1, lane, W, DD, ivS, GS, s);
        g_p63[r * DD + lane]      = (lane >= 1) ? v0 : 0.0f;
        g_p63[r * DD + lane + 32] = v1;
    }
}

// ============================================================================
// K2: per-batch-row head pipeline. grid B, ONE warp. (unchanged)
// ============================================================================
__global__ void __launch_bounds__(32) k_head(
    const float* __restrict__ ent, const float* __restrict__ bias_head,
    const int* __restrict__ u_idx, const int* __restrict__ r_idx,
    const float* __restrict__ fsh, const float* __restrict__ fst)
{
    int b = blockIdx.x, l = threadIdx.x;
    int u = u_idx[b], r = r_idx[b];
    float fsH = fsh[0], fsT = fst[0];

    float v0 = ent[(size_t)u * DD + l];
    float v1 = ent[(size_t)u * DD + l + 32];

    {   // y_sp = D (P^T x_sp): forward chain, then flip comp62
        const float* W  = &g_Wg[0][(size_t)r * DD * DD];
        const float* iv = &g_iv[0][r * DD];
        const float* G  = &g_G[0][r * 224];
        #pragma unroll 1
        for (int s = 0; s < 8; s++) apply_seg<true>(v0, v1, l, W, DD, iv, G, s);
    }
    if (l == 31) v1 *= fsH;

    // mobius_add(y, off_h)
    float oh0 = g_off[0][r * DD + l];
    float oh1 = g_off[0][r * DD + l + 32];
    float x2 = wbfly(fmaf(v0, v0, v1 * v1));
    float xy = wbfly(fmaf(v0, oh0, v1 * oh1));
    float y2  = g_off2[0][r];
    float A   = 1.0f + 2.0f * xy + y2;
    float Bc  = 1.0f - x2;
    float den = 1.0f + 2.0f * xy + x2 * y2 + 1e-15f;
    float rd  = 1.0f / den;
    float th0c = fmaf(A, v0, Bc * oh0) * rd;
    float th1c = fmaf(A, v1, Bc * oh1) * rd;

    // t~ = P D th_sp
    float t0 = th0c, t1 = th1c;
    if (l == 31) t1 *= fsT;
    {
        const float* W  = &g_Wg[1][(size_t)r * DD * DD];
        const float* iv = &g_iv[1][r * DD];
        const float* G  = &g_G[1][r * 224];
        #pragma unroll 1
        for (int s = 7; s >= 0; s--) apply_seg<false>(t0, t1, l, W, DD, iv, G, s);
    }
    g_ttl[b * DD + l]      = (l >= 1) ? t0 : 0.0f;
    g_ttl[b * DD + l + 32] = t1;

    // scalar pack
    float ot0 = g_off[1][r * DD + l];
    float ot1 = g_off[1][r * DD + l + 32];
    float e0  = (l >= 1) ? 1.0f : 0.0f;
    float pO2 = wbfly(fmaf(e0 * ot0, ot0,  ot1 * ot1));
    float pOT = wbfly(fmaf(e0 * ot0, th0c, ot1 * th1c));
    float pT2 = wbfly(fmaf(e0 * th0c, th0c, th1c * th1c));
    if (l == 0) {
        float* sc = &g_sc[b * 8];
        sc[0] = pO2;
        sc[1] = pOT;
        sc[2] = pT2;
        sc[3] = tanhf(bias_head[u]);
        sc[4] = th0c;
        sc[5] = ot0;
        sc[6] = g_off2[1][r];
        sc[7] = 0.0f;
    }
}

// ============================================================================
// K3: main scoring (unchanged). grid (B, N/128), block 128.
// ============================================================================
__global__ void __launch_bounds__(TMAIN) k_main(
    const float* __restrict__ ent, const float* __restrict__ bias_tail,
    const int* __restrict__ r_idx, const int* __restrict__ v_idx,
    const float* __restrict__ fst,
    float* __restrict__ out, int N)
{
    __shared__ __align__(16) float4 res4[TILE];
    __shared__ int   vs[TILE];
    __shared__ __align__(16) float pv[DD], ov[DD], tl[DD];
    __shared__ float scs[8];

    int b     = blockIdx.x;
    int tbase = blockIdx.y * TILE;
    int tid   = threadIdx.x;
    if (tbase >= N) return;
    int nt = min(TILE, N - tbase);
    int r  = r_idx[b];

    if (tid < DD) {
        pv[tid] = g_p63[r * DD + tid];
        ov[tid] = g_ofu[r * DD + tid];
        tl[tid] = g_ttl[b * DD + tid];
    }
    if (tid < 8) scs[tid] = g_sc[b * 8 + tid];
    vs[tid] = (tid < nt) ? v_idx[b * N + tbase + tid] : 0;
    float fsv  = fst[0];
    float fsm1 = fsv * fsv - 1.0f;
    __syncthreads();

    float btraw = bias_tail[vs[tid < nt ? tid : 0]];

    int h = tid & 7;
    int g = tid >> 3;
    float4 pa = ((const float4*)pv)[h], pb = ((const float4*)pv)[h + 8];
    float4 oa = ((const float4*)ov)[h], ob = ((const float4*)ov)[h + 8];
    float4 ta = ((const float4*)tl)[h], tb = ((const float4*)tl)[h + 8];

    #pragma unroll
    for (int i = 0; i < 8; i++) {
        int row = i * 16 + g;
        const float4* xr = (const float4*)(ent + (size_t)vs[row] * DD);
        float4 xa = xr[h];
        float4 xb = xr[h + 8];

        float s1 = fmaf(xa.x, pa.x, fmaf(xa.y, pa.y, fmaf(xa.z, pa.z, xa.w * pa.w)));
        s1 = fmaf(xb.x, pb.x, fmaf(xb.y, pb.y, fmaf(xb.z, pb.z, fmaf(xb.w, pb.w, s1))));
        float s2 = fmaf(xa.x, oa.x, fmaf(xa.y, oa.y, fmaf(xa.z, oa.z, xa.w * oa.w)));
        s2 = fmaf(xb.x, ob.x, fmaf(xb.y, ob.y, fmaf(xb.z, ob.z, fmaf(xb.w, ob.w, s2))));
        float s3 = fmaf(xa.x, ta.x, fmaf(xa.y, ta.y, fmaf(xa.z, ta.z, xa.w * ta.w)));
        s3 = fmaf(xb.x, tb.x, fmaf(xb.y, tb.y, fmaf(xb.z, tb.z, fmaf(xb.w, tb.w, s3))));

        #pragma unroll
        for (int o = 4; o; o >>= 1) {
            s1 += __shfl_down_sync(0xffffffffu, s1, o, 8);
            s2 += __shfl_down_sync(0xffffffffu, s2, o, 8);
            s3 += __shfl_down_sync(0xffffffffu, s3, o, 8);
        }
        if (h == 0) res4[row] = make_float4(s1, s2, s3, xa.x);
    }
    __syncthreads();

    if (tid < nt) {
        float4 rr = res4[tid];
        float s1 = rr.x, syo = rr.y, syt = rr.z, y0 = rr.w;

        float O2m = scs[0], OTm = scs[1], T2m = scs[2], thb = scs[3];
        float th0 = scs[4], off0 = scs[5], off2 = scs[6];

        float syy_m = fmaf(fsm1, s1 * s1, fmaf(y0, y0, -1.0f));
        float syy   = syy_m + y0 * y0;

        float A   = 1.0f + 2.0f * syo + off2;
        float Bv  = 1.0f - syy;
        float den = 1.0f + 2.0f * syo + syy * off2 + 1e-15f;
        float rd  = 1.0f / den;
        float a   = A * rd, bs = Bv * rd;
        float d0  = fmaf(a, y0, fmaf(bs, off0, -th0));
        float cross = fmaf(bs, syo - y0 * off0, -syt);
        float bterm = fmaf(bs, fmaf(bs, O2m, -2.0f * OTm), T2m);
        float sum1  = fmaf(a * a, syy_m, fmaf(2.0f * a, cross, bterm));
        float mkv   = sum1 - d0 * d0;

        out[(size_t)b * N + tbase + tid] = 8.0f - mkv + thb + tanhf(btraw);
    }
}

// ============================================================================
extern "C" void kernel_launch(void* const* d_in, const int* in_sizes, int n_in,
                              void* d_out, int out_size)
{
    (void)n_in; (void)out_size;
    const float* ent  = (const float*)d_in[0];
    const float* Wh   = (const float*)d_in[1];
    const float* Wtt  = (const float*)d_in[2];
    const float* rch  = (const float*)d_in[3];
    const float* dirh = (const float*)d_in[4];
    const float* rct  = (const float*)d_in[5];
    const float* dirt = (const float*)d_in[6];
    const float* bh   = (const float*)d_in[7];
    const float* bt   = (const float*)d_in[8];
    const float* fsh  = (const float*)d_in[9];
    const float* fst  = (const float*)d_in[10];
    const int* u_idx  = (const int*)d_in[11];
    const int* r_idx  = (const int*)d_in[12];
    const int* v_idx  = (const int*)d_in[13];
    float* out = (float*)d_out;

    int NR = in_sizes[3] / DD;       // 237
    int B  = in_sizes[11];           // 1024
    int N  = in_sizes[13] / B;       // 512
    int S  = (N + TILE - 1) / TILE;  // 4

    k_seg<<<dim3(NR, 2, 8), 64>>>(Wh, Wtt);
    k_offchain<<<dim3(NR, 2), 64>>>(rch, dirh, rct, dirt, fsh, fst);
    k_head<<<B, 32>>>(ent, bh, u_idx, r_idx, fsh, fst);
    k_main<<<dim3(B, S), TMAIN>>>(ent, bt, r_idx, v_idx, fst, out, N);
}

// round 16
// speedup vs baseline: 1.6544x; 1.1817x over previous
#include <cuda_runtime.h>
#include <cstdint>
#include <cstddef>

#define DM 63
#define DD 64
#define NR_MAX 256
#define B_MAX 2048
#define TMAIN 128
#define TILE  128
#define WSTR  65

// ---- scratch (static __device__ globals; no runtime allocation) ----
__device__ float g_Wg[2][(size_t)NR_MAX * DD * DD];   // gelu(W) rows [j*64+k], row 63 + col 63 zero
__device__ float g_iv[2][NR_MAX * DD];                // 2/s_j (j=63 -> 0)
__device__ float g_G [2][NR_MAX * 224];               // intra-segment Gram pairs
__device__ float g_off[2][NR_MAX * DD];               // mobius offset per relation
__device__ float g_off2[2][NR_MAX];                   // sum(off^2)
__device__ float g_p63[NR_MAX * DD];                  // tail: P e62 (unscaled last col), [0]=0
__device__ float g_ofu[NR_MAX * DD];                  // tail: P D off_sp, [0]=off0
__device__ float g_ttl[B_MAX * DD];                   // tail: P D th_sp per b, [0]=0
__device__ float g_sc[B_MAX * 8];                     // {O2m,OTm,T2m,thb,th0,off0,off2,-}

__device__ __constant__ int c_pa[28] = {0,0,1,0,1,2,0,1,2,3,0,1,2,3,4,0,1,2,3,4,5,0,1,2,3,4,5,6};
__device__ __constant__ int c_pb[28] = {1,2,2,3,3,3,4,4,4,4,5,5,5,5,5,6,6,6,6,6,6,7,7,7,7,7,7,7};

__device__ __forceinline__ float gelu_exact(float x) {
    return 0.5f * x * (1.0f + erff(x * 0.70710678118654752f));
}

__device__ __forceinline__ float wbfly(float v) {
    #pragma unroll
    for (int o = 16; o; o >>= 1) v += __shfl_xor_sync(0xffffffffu, v, o);
    return v;
}

// ============================================================================
// Rank-8 reflection segment applied to a warp-held vector.
// lane l owns full-vec comps l (slot0) and l+32 (slot1); chain comp c lives at
// full idx c+1. FWD: i=0..7 (y = H1..H63 x). REV: i=7..0 (P v). Row 63 pad
// (w=0, iv=0) makes the last step a no-op.
// ============================================================================
template<bool FWD>
__device__ __forceinline__ void apply_seg(
    float& v0, float& v1, int lane,
    const float* __restrict__ W, int wstride,
    const float* __restrict__ iv, const float* __restrict__ G, int seg)
{
    int lo = seg * 8;
    float w0[8], w1[8], d[8], ivv[8], g[28];
    #pragma unroll
    for (int i = 0; i < 8; i++) {
        const float* row = W + (size_t)(lo + i) * wstride;
        w0[i] = (lane >= 1) ? row[lane - 1] : 0.0f;
        w1[i] = row[lane + 31];
        ivv[i] = iv[lo + i];
    }
    #pragma unroll
    for (int p = 0; p < 28; p++) g[p] = G[seg * 28 + p];
    #pragma unroll
    for (int i = 0; i < 8; i++) d[i] = fmaf(w0[i], v0, w1[i] * v1);
    #pragma unroll
    for (int o = 16; o; o >>= 1) {
        #pragma unroll
        for (int i = 0; i < 8; i++) d[i] += __shfl_xor_sync(0xffffffffu, d[i], o);
    }
    float c[8];
    if (FWD) {
        c[0] = d[0] * ivv[0];
        c[1] = (d[1] - c[0]*g[0]) * ivv[1];
        c[2] = (d[2] - c[0]*g[1] - c[1]*g[2]) * ivv[2];
        c[3] = (d[3] - c[0]*g[3] - c[1]*g[4] - c[2]*g[5]) * ivv[3];
        c[4] = (d[4] - c[0]*g[6] - c[1]*g[7] - c[2]*g[8] - c[3]*g[9]) * ivv[4];
        c[5] = (d[5] - c[0]*g[10] - c[1]*g[11] - c[2]*g[12] - c[3]*g[13] - c[4]*g[14]) * ivv[5];
        c[6] = (d[6] - c[0]*g[15] - c[1]*g[16] - c[2]*g[17] - c[3]*g[18] - c[4]*g[19] - c[5]*g[20]) * ivv[6];
        c[7] = (d[7] - c[0]*g[21] - c[1]*g[22] - c[2]*g[23] - c[3]*g[24] - c[4]*g[25] - c[5]*g[26] - c[6]*g[27]) * ivv[7];
    } else {
        c[7] = d[7] * ivv[7];
        c[6] = (d[6] - c[7]*g[27]) * ivv[6];
        c[5] = (d[5] - c[7]*g[26] - c[6]*g[20]) * ivv[5];
        c[4] = (d[4] - c[7]*g[25] - c[6]*g[19] - c[5]*g[14]) * ivv[4];
        c[3] = (d[3] - c[7]*g[24] - c[6]*g[18] - c[5]*g[13] - c[4]*g[9]) * ivv[3];
        c[2] = (d[2] - c[7]*g[23] - c[6]*g[17] - c[5]*g[12] - c[4]*g[8] - c[3]*g[5]) * ivv[2];
        c[1] = (d[1] - c[7]*g[22] - c[6]*g[16] - c[5]*g[11] - c[4]*g[7] - c[3]*g[4] - c[2]*g[2]) * ivv[1];
        c[0] = (d[0] - c[7]*g[21] - c[6]*g[15] - c[5]*g[10] - c[4]*g[6] - c[3]*g[3] - c[2]*g[1] - c[1]*g[0]) * ivv[0];
    }
    float s0 = 0.0f, s1 = 0.0f;
    #pragma unroll
    for (int i = 0; i < 8; i++) { s0 = fmaf(c[i], w0[i], s0); s1 = fmaf(c[i], w1[i], s1); }
    v0 -= s0; v1 -= s1;
}

// ============================================================================
// K1: per-segment gelu + norms + Gram; z==0 block also computes the expmap
// offset (W-independent). grid (NR, 2, 8), block 64.
// ============================================================================
__global__ void __launch_bounds__(64) k_seg(
    const float* __restrict__ Wh,  const float* __restrict__ Wtt,
    const float* __restrict__ rch, const float* __restrict__ dirh,
    const float* __restrict__ rct, const float* __restrict__ dirt)
{
    int r = blockIdx.x, side = blockIdx.y, seg = blockIdx.z;
    const float* Wemb = side ? Wtt : Wh;
    __shared__ __align__(16) float WgS[8][WSTR];

    int tid = threadIdx.x, lane = tid & 31, wid = tid >> 5;
    float* gW = &g_Wg[side][(size_t)r * DD * DD];
    int j0 = seg * 8;

    // gelu 8 rows -> smem + global (pads: j==63 or k==63 -> 0)
    const float* wb = Wemb + (size_t)r * DM * DM;
    #pragma unroll
    for (int ii = 0; ii < 8; ii++) {
        int idx = ii * 64 + tid;          // 0..511
        int jj = idx >> 6, k = idx & 63;
        int j = j0 + jj;
        float v = 0.0f;
        if (j < DM && k < DM) v = gelu_exact(wb[j * DM + k]);
        WgS[jj][k] = v;
        gW[(size_t)j * DD + k] = v;
    }
    __syncthreads();

    // 36 tasks: t<8 norms -> iv; t in [8,36) Gram pairs
    if (tid < 36) {
        const float *ra, *rb;
        if (tid < 8) { ra = rb = WgS[tid]; }
        else { int q = tid - 8; ra = WgS[c_pa[q]]; rb = WgS[c_pb[q]]; }
        float a0 = 0, a1 = 0, a2 = 0, a3 = 0;
        #pragma unroll
        for (int k = 0; k < DD; k += 4) {
            a0 = fmaf(ra[k    ], rb[k    ], a0);
            a1 = fmaf(ra[k + 1], rb[k + 1], a1);
            a2 = fmaf(ra[k + 2], rb[k + 2], a2);
            a3 = fmaf(ra[k + 3], rb[k + 3], a3);
        }
        float dot = (a0 + a1) + (a2 + a3);
        if (tid < 8) {
            int j = j0 + tid;
            g_iv[side][r * DD + j] = (j < DM) ? 2.0f / dot : 0.0f;
        } else {
            g_G[side][r * 224 + seg * 28 + (tid - 8)] = dot;
        }
    }

    // offset = expmap(c, 0.1 * normalize(d + <c,d> c)) — z==0 block, warp 1
    // (warp 0 is busy with dot tasks; warp 1 only has tasks 32..35)
    if (seg == 0 && wid == 1) {
        const float* rc = side ? rct  : rch;
        const float* dw = side ? dirt : dirh;
        float cv0 = rc[r * DD + lane], cv1 = rc[r * DD + lane + 32];
        float dv0 = dw[r * DD + lane], dv1 = dw[r * DD + lane + 32];
        float inner = wbfly(fmaf(cv0, dv0, cv1 * dv1));
        float t0 = fmaf(inner, cv0, dv0), t1 = fmaf(inner, cv1, dv1);
        float tn2 = wbfly(fmaf(t0, t0, t1 * t1));
        float inv = 1.0f / (sqrtf(tn2) + 1e-6f);
        float u0v = 0.1f * t0 * inv, u1v = 0.1f * t1 * inv;
        float su2 = wbfly(fmaf(u0v, u0v, u1v * u1v));
        float ut  = __shfl_sync(0xffffffffu, u0v, 0);
        float lin = su2 - 2.0f * ut * ut;
        float nrm = fminf(sqrtf(fmaxf(lin, 1e-8f)), 2.5f);
        float ch = coshf(nrm), sh = sinhf(nrm) / nrm;
        float o0 = fmaf(ch, cv0, sh * u0v);
        float o1 = fmaf(ch, cv1, sh * u1v);
        g_off[side][r * DD + lane]      = o0;
        g_off[side][r * DD + lane + 32] = o1;
        float o2 = wbfly(fmaf(o0, o0, o1 * o1));
        if (lane == 0) g_off2[side][r] = o2;
    }
}

// ============================================================================
// K2: merged head pipeline + side-1 relation chains. grid (B/2 + NR), block 64.
//   blk < B/2 : two head rows (one per warp) — fwd chain, mobius, rev chain,
//               t~ + scalar pack.
//   blk >= B/2: relation r = blk - B/2 — warp0: õ chain, warp1: p63 chain.
// ============================================================================
__global__ void __launch_bounds__(64) k_hc(
    const float* __restrict__ ent, const float* __restrict__ bias_head,
    const int* __restrict__ u_idx, const int* __restrict__ r_idx,
    const float* __restrict__ fsh, const float* __restrict__ fst, int Bh)
{
    __shared__ float ivS[DD];
    __shared__ float GS[224];

    int blk = blockIdx.x;
    int tid = threadIdx.x, lane = tid & 31, wid = tid >> 5;

    if (blk < Bh) {
        // ---- head pipeline: row b = blk*2 + wid ----
        int b = blk * 2 + wid;
        int u = u_idx[b], r = r_idx[b];
        float fsH = fsh[0], fsT = fst[0];
        int l = lane;

        float v0 = ent[(size_t)u * DD + l];
        float v1 = ent[(size_t)u * DD + l + 32];

        {   // y_sp = D (P^T x_sp): forward chain, then flip comp62
            const float* W  = &g_Wg[0][(size_t)r * DD * DD];
            const float* iv = &g_iv[0][r * DD];
            const float* G  = &g_G[0][r * 224];
            #pragma unroll 1
            for (int s = 0; s < 8; s++) apply_seg<true>(v0, v1, l, W, DD, iv, G, s);
        }
        if (l == 31) v1 *= fsH;

        // mobius_add(y, off_h)
        float oh0 = g_off[0][r * DD + l];
        float oh1 = g_off[0][r * DD + l + 32];
        float x2 = wbfly(fmaf(v0, v0, v1 * v1));
        float xy = wbfly(fmaf(v0, oh0, v1 * oh1));
        float y2  = g_off2[0][r];
        float A   = 1.0f + 2.0f * xy + y2;
        float Bc  = 1.0f - x2;
        float den = 1.0f + 2.0f * xy + x2 * y2 + 1e-15f;
        float rd  = 1.0f / den;
        float th0c = fmaf(A, v0, Bc * oh0) * rd;
        float th1c = fmaf(A, v1, Bc * oh1) * rd;

        // t~ = P D th_sp
        float t0 = th0c, t1 = th1c;
        if (l == 31) t1 *= fsT;
        {
            const float* W  = &g_Wg[1][(size_t)r * DD * DD];
            const float* iv = &g_iv[1][r * DD];
            const float* G  = &g_G[1][r * 224];
            #pragma unroll 1
            for (int s = 7; s >= 0; s--) apply_seg<false>(t0, t1, l, W, DD, iv, G, s);
        }
        g_ttl[b * DD + l]      = (l >= 1) ? t0 : 0.0f;
        g_ttl[b * DD + l + 32] = t1;

        // scalar pack
        float ot0 = g_off[1][r * DD + l];
        float ot1 = g_off[1][r * DD + l + 32];
        float e0  = (l >= 1) ? 1.0f : 0.0f;
        float pO2 = wbfly(fmaf(e0 * ot0, ot0,  ot1 * ot1));
        float pOT = wbfly(fmaf(e0 * ot0, th0c, ot1 * th1c));
        float pT2 = wbfly(fmaf(e0 * th0c, th0c, th1c * th1c));
        if (l == 0) {
            float* sc = &g_sc[b * 8];
            sc[0] = pO2;
            sc[1] = pOT;
            sc[2] = pT2;
            sc[3] = tanhf(bias_head[u]);
            sc[4] = th0c;
            sc[5] = ot0;
            sc[6] = g_off2[1][r];
            sc[7] = 0.0f;
        }
    } else {
        // ---- side-1 relation chains for r = blk - Bh ----
        int r = blk - Bh;
        float fs = fst[0];

        ivS[tid] = g_iv[1][r * DD + tid];
        for (int i = tid; i < 224; i += 64) GS[i] = g_G[1][r * 224 + i];
        __syncthreads();

        const float* W = &g_Wg[1][(size_t)r * DD * DD];
        if (wid == 0) {
            // õ = P D off_sp : reverse chain on flip-scaled offset spatial part
            float o0 = g_off[1][r * DD + lane];
            float o1 = g_off[1][r * DD + lane + 32];
            float off0save = __shfl_sync(0xffffffffu, o0, 0);
            float v0 = (lane >= 1) ? o0 : 0.0f;
            float v1 = o1;
            if (lane == 31) v1 *= fs;
            #pragma unroll 1
            for (int s = 7; s >= 0; s--) apply_seg<false>(v0, v1, lane, W, DD, ivS, GS, s);
            g_ofu[r * DD + lane]      = (lane >= 1) ? v0 : off0save;
            g_ofu[r * DD + lane + 32] = v1;
        } else {
            // p63 = P e62 : reverse chain on unit vector (no flip)
            float v0 = 0.0f;
            float v1 = (lane == 31) ? 1.0f : 0.0f;
            #pragma unroll 1
            for (int s = 7; s >= 0; s--) apply_seg<false>(v0, v1, lane, W, DD, ivS, GS, s);
            g_p63[r * DD + lane]      = (lane >= 1) ? v0 : 0.0f;
            g_p63[r * DD + lane + 32] = v1;
        }
    }
}

// ============================================================================
// K3: main scoring (unchanged). grid (B, N/128), block 128.
// ============================================================================
__global__ void __launch_bounds__(TMAIN) k_main(
    const float* __restrict__ ent, const float* __restrict__ bias_tail,
    const int* __restrict__ r_idx, const int* __restrict__ v_idx,
    const float* __restrict__ fst,
    float* __restrict__ out, int N)
{
    __shared__ __align__(16) float4 res4[TILE];
    __shared__ int   vs[TILE];
    __shared__ __align__(16) float pv[DD], ov[DD], tl[DD];
    __shared__ float scs[8];

    int b     = blockIdx.x;
    int tbase = blockIdx.y * TILE;
    int tid   = threadIdx.x;
    if (tbase >= N) return;
    int nt = min(TILE, N - tbase);
    int r  = r_idx[b];

    if (tid < DD) {
        pv[tid] = g_p63[r * DD + tid];
        ov[tid] = g_ofu[r * DD + tid];
        tl[tid] = g_ttl[b * DD + tid];
    }
    if (tid < 8) scs[tid] = g_sc[b * 8 + tid];
    vs[tid] = (tid < nt) ? v_idx[b * N + tbase + tid] : 0;
    float fsv  = fst[0];
    float fsm1 = fsv * fsv - 1.0f;
    __syncthreads();

    float btraw = bias_tail[vs[tid < nt ? tid : 0]];

    int h = tid & 7;
    int g = tid >> 3;
    float4 pa = ((const float4*)pv)[h], pb = ((const float4*)pv)[h + 8];
    float4 oa = ((const float4*)ov)[h], ob = ((const float4*)ov)[h + 8];
    float4 ta = ((const float4*)tl)[h], tb = ((const float4*)tl)[h + 8];

    #pragma unroll
    for (int i = 0; i < 8; i++) {
        int row = i * 16 + g;
        const float4* xr = (const float4*)(ent + (size_t)vs[row] * DD);
        float4 xa = xr[h];
        float4 xb = xr[h + 8];

        float s1 = fmaf(xa.x, pa.x, fmaf(xa.y, pa.y, fmaf(xa.z, pa.z, xa.w * pa.w)));
        s1 = fmaf(xb.x, pb.x, fmaf(xb.y, pb.y, fmaf(xb.z, pb.z, fmaf(xb.w, pb.w, s1))));
        float s2 = fmaf(xa.x, oa.x, fmaf(xa.y, oa.y, fmaf(xa.z, oa.z, xa.w * oa.w)));
        s2 = fmaf(xb.x, ob.x, fmaf(xb.y, ob.y, fmaf(xb.z, ob.z, fmaf(xb.w, ob.w, s2))));
        float s3 = fmaf(xa.x, ta.x, fmaf(xa.y, ta.y, fmaf(xa.z, ta.z, xa.w * ta.w)));
        s3 = fmaf(xb.x, tb.x, fmaf(xb.y, tb.y, fmaf(xb.z, tb.z, fmaf(xb.w, tb.w, s3))));

        #pragma unroll
        for (int o = 4; o; o >>= 1) {
            s1 += __shfl_down_sync(0xffffffffu, s1, o, 8);
            s2 += __shfl_down_sync(0xffffffffu, s2, o, 8);
            s3 += __shfl_down_sync(0xffffffffu, s3, o, 8);
        }
        if (h == 0) res4[row] = make_float4(s1, s2, s3, xa.x);
    }
    __syncthreads();

    if (tid < nt) {
        float4 rr = res4[tid];
        float s1 = rr.x, syo = rr.y, syt = rr.z, y0 = rr.w;

        float O2m = scs[0], OTm = scs[1], T2m = scs[2], thb = scs[3];
        float th0 = scs[4], off0 = scs[5], off2 = scs[6];

        float syy_m = fmaf(fsm1, s1 * s1, fmaf(y0, y0, -1.0f));
        float syy   = syy_m + y0 * y0;

        float A   = 1.0f + 2.0f * syo + off2;
        float Bv  = 1.0f - syy;
        float den = 1.0f + 2.0f * syo + syy * off2 + 1e-15f;
        float rd  = 1.0f / den;
        float a   = A * rd, bs = Bv * rd;
        float d0  = fmaf(a, y0, fmaf(bs, off0, -th0));
        float cross = fmaf(bs, syo - y0 * off0, -syt);
        float bterm = fmaf(bs, fmaf(bs, O2m, -2.0f * OTm), T2m);
        float sum1  = fmaf(a * a, syy_m, fmaf(2.0f * a, cross, bterm));
        float mkv   = sum1 - d0 * d0;

        out[(size_t)b * N + tbase + tid] = 8.0f - mkv + thb + tanhf(btraw);
    }
}

// ============================================================================
extern "C" void kernel_launch(void* const* d_in, const int* in_sizes, int n_in,
                              void* d_out, int out_size)
{
    (void)n_in; (void)out_size;
    const float* ent  = (const float*)d_in[0];
    const float* Wh   = (const float*)d_in[1];
    const float* Wtt  = (const float*)d_in[2];
    const float* rch  = (const float*)d_in[3];
    const float* dirh = (const float*)d_in[4];
    const float* rct  = (const float*)d_in[5];
    const float* dirt = (const float*)d_in[6];
    const float* bh   = (const float*)d_in[7];
    const float* bt   = (const float*)d_in[8];
    const float* fsh  = (const float*)d_in[9];
    const float* fst  = (const float*)d_in[10];
    const int* u_idx  = (const int*)d_in[11];
    const int* r_idx  = (const int*)d_in[12];
    const int* v_idx  = (const int*)d_in[13];
    float* out = (float*)d_out;

    int NR = in_sizes[3] / DD;       // 237
    int B  = in_sizes[11];           // 1024
    int N  = in_sizes[13] / B;       // 512
    int S  = (N + TILE - 1) / TILE;  // 4
    int Bh = B / 2;                  // 512 head blocks (2 rows each)

    k_seg<<<dim3(NR, 2, 8), 64>>>(Wh, Wtt, rch, dirh, rct, dirt);
    k_hc<<<Bh + NR, 64>>>(ent, bh, u_idx, r_idx, fsh, fst, Bh);
    k_main<<<dim3(B, S), TMAIN>>>(ent, bt, r_idx, v_idx, fst, out, N);
}